// round 4
// baseline (speedup 1.0000x reference)
#include <cuda_runtime.h>
#include <cuda_bf16.h>
#include <math.h>

// Problem dims (fixed by the reference)
#define BB 4
#define SS 2048
#define DD 1024
#define FF 4096

// ---------------- scratch (no allocs allowed -> __device__ globals) -------
__device__ float g_ln1[(size_t)BB * SS * DD];
__device__ float g_Q  [(size_t)BB * SS * DD];
__device__ float g_K  [(size_t)BB * SS * DD];
__device__ float g_V  [(size_t)BB * SS * DD];
__device__ float g_scores[(size_t)BB * SS * SS];
__device__ float g_x1 [(size_t)BB * SS * DD];
__device__ float g_ln2[(size_t)BB * SS * DD];
__device__ float g_H  [(size_t)BB * SS * FF];

// ---------------- LayerNorm: one block per row (D=1024, 256 thr) ---------
__global__ __launch_bounds__(256)
void layernorm_kernel(const float* __restrict__ x,
                      const float* __restrict__ gamma,
                      const float* __restrict__ beta,
                      float* __restrict__ out)
{
    const int row = blockIdx.x;
    const int tid = threadIdx.x;
    const float4* xr = (const float4*)(x + (size_t)row * DD);
    float4 v = xr[tid];

    float s  = v.x + v.y + v.z + v.w;
    float sq = v.x * v.x + v.y * v.y + v.z * v.z + v.w * v.w;

    __shared__ float ws[8], wq[8];
    #pragma unroll
    for (int o = 16; o; o >>= 1) {
        s  += __shfl_xor_sync(0xffffffffu, s,  o);
        sq += __shfl_xor_sync(0xffffffffu, sq, o);
    }
    const int w = tid >> 5, l = tid & 31;
    if (l == 0) { ws[w] = s; wq[w] = sq; }
    __syncthreads();
    if (w == 0) {
        s  = (l < 8) ? ws[l] : 0.f;
        sq = (l < 8) ? wq[l] : 0.f;
        #pragma unroll
        for (int o = 4; o; o >>= 1) {
            s  += __shfl_xor_sync(0xffffffffu, s,  o);
            sq += __shfl_xor_sync(0xffffffffu, sq, o);
        }
        if (l == 0) { ws[0] = s; wq[0] = sq; }
    }
    __syncthreads();

    const float mean = ws[0] * (1.f / (float)DD);
    const float var  = wq[0] * (1.f / (float)DD) - mean * mean;
    const float rstd = rsqrtf(var + 1e-5f);

    float4 g = ((const float4*)gamma)[tid];
    float4 b = ((const float4*)beta )[tid];
    float4 o4;
    o4.x = g.x * ((v.x - mean) * rstd) + b.x;
    o4.y = g.y * ((v.y - mean) * rstd) + b.y;
    o4.z = g.z * ((v.z - mean) * rstd) + b.z;
    o4.w = g.w * ((v.w - mean) * rstd) + b.w;
    ((float4*)(out + (size_t)row * DD))[tid] = o4;
}

// ---------------- causal softmax, in-place, one block per row ------------
__global__ __launch_bounds__(256)
void softmax_kernel(float* __restrict__ scores)
{
    const int row = blockIdx.x;          // 0 .. B*S-1
    const int b = row >> 11;             // / 2048
    const int i = row & (SS - 1);
    float* p = scores + (size_t)b * SS * SS + (size_t)i * SS;
    const int len = i + 1;
    const int tid = threadIdx.x;
    __shared__ float sh[8];

    // max
    float m = -1e30f;
    for (int j = tid; j < len; j += 256) m = fmaxf(m, p[j]);
    #pragma unroll
    for (int o = 16; o; o >>= 1) m = fmaxf(m, __shfl_xor_sync(0xffffffffu, m, o));
    const int w = tid >> 5, l = tid & 31;
    if (l == 0) sh[w] = m;
    __syncthreads();
    if (w == 0) {
        m = (l < 8) ? sh[l] : -1e30f;
        #pragma unroll
        for (int o = 4; o; o >>= 1) m = fmaxf(m, __shfl_xor_sync(0xffffffffu, m, o));
        if (l == 0) sh[0] = m;
    }
    __syncthreads();
    m = sh[0];
    __syncthreads();

    // exp + sum
    float sum = 0.f;
    for (int j = tid; j < len; j += 256) {
        float e = __expf(p[j] - m);
        p[j] = e;
        sum += e;
    }
    #pragma unroll
    for (int o = 16; o; o >>= 1) sum += __shfl_xor_sync(0xffffffffu, sum, o);
    if (l == 0) sh[w] = sum;
    __syncthreads();
    if (w == 0) {
        sum = (l < 8) ? sh[l] : 0.f;
        #pragma unroll
        for (int o = 4; o; o >>= 1) sum += __shfl_xor_sync(0xffffffffu, sum, o);
        if (l == 0) sh[0] = sum;
    }
    __syncthreads();
    const float inv = 1.f / sh[0];

    // normalize; zero out up to the next 128 boundary so the K-limited
    // P@V GEMM (which reads k < round_up_128(row_tile)) sees zeros there.
    const int lenp = (len + 127) & ~127;
    for (int j = tid; j < lenp; j += 256)
        p[j] = (j < len) ? p[j] * inv : 0.f;
}

// ---------------- generic 128x128x8 SGEMM, 8x8 per thread ----------------
// EPI: 0=none  1=alpha-scale  2=+bias,ReLU  3=+bias+residual  4=+residual
#define BM 128
#define BN 128
#define BK 8
#define TM 8
#define TN 8

template <bool TRANSB, int EPI, bool CSKIP, bool KLIM>
__global__ __launch_bounds__(256)
void gemm_kernel(const float* __restrict__ A, const float* __restrict__ B,
                 float* __restrict__ C,
                 const float* __restrict__ bias, const float* __restrict__ Res,
                 int M, int N, int K,
                 long strideA, long strideB, long strideC, long strideR,
                 float alpha)
{
    const int bx = blockIdx.x, by = blockIdx.y, bz = blockIdx.z;
    const int m0 = by * BM, n0 = bx * BN;
    if (CSKIP && n0 >= m0 + BM) return;   // fully above the causal diagonal

    A += (size_t)bz * strideA;
    B += (size_t)bz * strideB;
    C += (size_t)bz * strideC;
    if (EPI == 3 || EPI == 4) Res += (size_t)bz * strideR;

    __shared__ float As[BK][BM];
    __shared__ float Bs[BK][BN];

    const int tid = threadIdx.x;
    const int rowA = tid >> 1;            // 0..127
    const int colA = (tid & 1) * 4;       // 0 / 4
    const int rowB = tid >> 5;            // 0..7
    const int colB = (tid & 31) * 4;      // 0..124
    const int ty = tid >> 4;              // 0..15
    const int tx = tid & 15;              // 0..15

    int kend = K;
    if (KLIM) { int lim = m0 + BM; kend = lim < K ? lim : K; }

    float acc[TM][TN];
    #pragma unroll
    for (int i = 0; i < TM; i++)
        #pragma unroll
        for (int j = 0; j < TN; j++) acc[i][j] = 0.f;

    for (int k0 = 0; k0 < kend; k0 += BK) {
        float4 av = *(const float4*)(A + (size_t)(m0 + rowA) * K + k0 + colA);
        As[colA + 0][rowA] = av.x;
        As[colA + 1][rowA] = av.y;
        As[colA + 2][rowA] = av.z;
        As[colA + 3][rowA] = av.w;
        if (!TRANSB) {
            float4 bv = *(const float4*)(B + (size_t)(k0 + rowB) * N + n0 + colB);
            *(float4*)(&Bs[rowB][colB]) = bv;
        } else {
            float4 bv = *(const float4*)(B + (size_t)(n0 + rowA) * K + k0 + colA);
            Bs[colA + 0][rowA] = bv.x;
            Bs[colA + 1][rowA] = bv.y;
            Bs[colA + 2][rowA] = bv.z;
            Bs[colA + 3][rowA] = bv.w;
        }
        __syncthreads();

        #pragma unroll
        for (int k = 0; k < BK; k++) {
            float a[TM], b[TN];
            #pragma unroll
            for (int i = 0; i < TM; i++) a[i] = As[k][ty * TM + i];
            #pragma unroll
            for (int j = 0; j < TN; j++) b[j] = Bs[k][tx * TN + j];
            #pragma unroll
            for (int i = 0; i < TM; i++)
                #pragma unroll
                for (int j = 0; j < TN; j++)
                    acc[i][j] = fmaf(a[i], b[j], acc[i][j]);
        }
        __syncthreads();
    }

    // ---- epilogue (float4 stores; thread owns 8 contiguous cols) ----
    #pragma unroll
    for (int i = 0; i < TM; i++) {
        const int r = m0 + ty * TM + i;
        const size_t base = (size_t)r * N + n0 + tx * TN;
        #pragma unroll
        for (int jj = 0; jj < TN; jj += 4) {
            float4 v;
            v.x = acc[i][jj + 0]; v.y = acc[i][jj + 1];
            v.z = acc[i][jj + 2]; v.w = acc[i][jj + 3];
            const int c = n0 + tx * TN + jj;
            if (EPI == 1) {
                v.x *= alpha; v.y *= alpha; v.z *= alpha; v.w *= alpha;
            } else if (EPI == 2) {
                float4 bb = *(const float4*)(bias + c);
                v.x = fmaxf(v.x + bb.x, 0.f); v.y = fmaxf(v.y + bb.y, 0.f);
                v.z = fmaxf(v.z + bb.z, 0.f); v.w = fmaxf(v.w + bb.w, 0.f);
            } else if (EPI == 3) {
                float4 bb = *(const float4*)(bias + c);
                float4 rr = *(const float4*)(Res + base + jj);
                v.x += bb.x + rr.x; v.y += bb.y + rr.y;
                v.z += bb.z + rr.z; v.w += bb.w + rr.w;
            } else if (EPI == 4) {
                float4 rr = *(const float4*)(Res + base + jj);
                v.x += rr.x; v.y += rr.y; v.z += rr.z; v.w += rr.w;
            }
            *(float4*)(C + base + jj) = v;
        }
    }
}

// ---------------- launcher ----------------
extern "C" void kernel_launch(void* const* d_in, const int* in_sizes, int n_in,
                              void* d_out, int out_size)
{
    (void)in_sizes; (void)n_in; (void)out_size;
    const float* x      = (const float*)d_in[0];
    const float* Qw     = (const float*)d_in[1];
    const float* Kw     = (const float*)d_in[2];
    const float* Vw     = (const float*)d_in[3];
    const float* w1     = (const float*)d_in[4];
    const float* b1     = (const float*)d_in[5];
    const float* w2     = (const float*)d_in[6];
    const float* b2     = (const float*)d_in[7];
    const float* gamma1 = (const float*)d_in[8];
    const float* beta1  = (const float*)d_in[9];
    const float* gamma2 = (const float*)d_in[10];
    const float* beta2  = (const float*)d_in[11];
    float* out = (float*)d_out;

    float *pln1, *pQ, *pK, *pV, *pS, *px1, *pln2, *pH;
    cudaGetSymbolAddress((void**)&pln1, g_ln1);
    cudaGetSymbolAddress((void**)&pQ,   g_Q);
    cudaGetSymbolAddress((void**)&pK,   g_K);
    cudaGetSymbolAddress((void**)&pV,   g_V);
    cudaGetSymbolAddress((void**)&pS,   g_scores);
    cudaGetSymbolAddress((void**)&px1,  g_x1);
    cudaGetSymbolAddress((void**)&pln2, g_ln2);
    cudaGetSymbolAddress((void**)&pH,   g_H);

    const int MR = BB * SS;          // 8192 rows
    dim3 blk(256);

    // 1) LN1
    layernorm_kernel<<<MR, blk>>>(x, gamma1, beta1, pln1);

    // 2) Q, K, V projections (M=8192, N=K=1024)
    dim3 gqkv(DD / BN, MR / BM, 1);
    gemm_kernel<false, 0, false, false><<<gqkv, blk>>>(pln1, Qw, pQ, nullptr, nullptr,
        MR, DD, DD, 0, 0, 0, 0, 1.f);
    gemm_kernel<false, 0, false, false><<<gqkv, blk>>>(pln1, Kw, pK, nullptr, nullptr,
        MR, DD, DD, 0, 0, 0, 0, 1.f);
    gemm_kernel<false, 0, false, false><<<gqkv, blk>>>(pln1, Vw, pV, nullptr, nullptr,
        MR, DD, DD, 0, 0, 0, 0, 1.f);

    // 3) scores = (Q @ K^T) / sqrt(D), causal tiles only
    dim3 gsc(SS / BN, SS / BM, BB);
    gemm_kernel<true, 1, true, false><<<gsc, blk>>>(pQ, pK, pS, nullptr, nullptr,
        SS, SS, DD, (long)SS * DD, (long)SS * DD, (long)SS * SS, 0, 0.03125f);

    // 4) causal softmax in-place (zeros to 128-boundary for the K-limited PV)
    softmax_kernel<<<MR, blk>>>(pS);

    // 5) attn = P @ V + x   (K-limited to the causal band, residual fused)
    dim3 gpv(DD / BN, SS / BM, BB);
    gemm_kernel<false, 4, false, true><<<gpv, blk>>>(pS, pV, px1, nullptr, x,
        SS, DD, SS, (long)SS * SS, (long)SS * DD, (long)SS * DD, (long)SS * DD, 1.f);

    // 6) LN2
    layernorm_kernel<<<MR, blk>>>(px1, gamma2, beta2, pln2);

    // 7) H = relu(ln2 @ w1 + b1)   (M=8192, N=4096, K=1024)
    dim3 gf1(FF / BN, MR / BM, 1);
    gemm_kernel<false, 2, false, false><<<gf1, blk>>>(pln2, w1, pH, b1, nullptr,
        MR, FF, DD, 0, 0, 0, 0, 1.f);

    // 8) out = H @ w2 + b2 + x1    (M=8192, N=1024, K=4096)
    dim3 gf2(DD / BN, MR / BM, 1);
    gemm_kernel<false, 3, false, false><<<gf2, blk>>>(pH, w2, out, b2, px1,
        MR, DD, FF, 0, 0, 0, 0, 1.f);
}

// round 7
// speedup vs baseline: 3.4471x; 3.4471x over previous
#include <cuda_runtime.h>
#include <cstdint>
#include <math.h>

#define BB 4
#define SS 2048
#define DD 1024
#define FF 4096

// ---------------- scratch (__device__ globals; no allocs allowed) --------
__device__ float g_ln1[(size_t)BB * SS * DD];
__device__ float g_Q  [(size_t)BB * SS * DD];
__device__ float g_K  [(size_t)BB * SS * DD];
__device__ float g_Vt [(size_t)BB * DD * SS];   // V transposed: [b][d][s]
__device__ float g_S  [(size_t)BB * SS * SS];
__device__ float g_x1 [(size_t)BB * SS * DD];
__device__ float g_ln2[(size_t)BB * SS * DD];
__device__ float g_H  [(size_t)BB * SS * FF];
__device__ float g_Qwt[(size_t)DD * DD];
__device__ float g_Kwt[(size_t)DD * DD];
__device__ float g_Vwt[(size_t)DD * DD];
__device__ float g_w1t[(size_t)DD * FF];
__device__ float g_w2t[(size_t)DD * FF];

// ---------------- helpers -------------------------------------------------
__device__ __forceinline__ uint32_t smem_u32(const void* p) {
    uint32_t a;
    asm("{ .reg .u64 t; cvta.to.shared.u64 t, %1; cvt.u32.u64 %0, t; }"
        : "=r"(a) : "l"(p));
    return a;
}
__device__ __forceinline__ float rna_tf32(float x) {
    uint32_t u;
    asm("cvt.rna.tf32.f32 %0, %1;" : "=r"(u) : "f"(x));
    return __uint_as_float(u);
}
__device__ __forceinline__ void cpa16(uint32_t dst, const void* src) {
    asm volatile("cp.async.cg.shared.global [%0], [%1], 16;\n"
                 :: "r"(dst), "l"(src));
}
__device__ __forceinline__ void cp_commit() {
    asm volatile("cp.async.commit_group;\n" ::: "memory");
}
__device__ __forceinline__ void cp_wait1() {
    asm volatile("cp.async.wait_group 1;\n" ::: "memory");
}
__device__ __forceinline__ void cp_wait0() {
    asm volatile("cp.async.wait_group 0;\n" ::: "memory");
}
__device__ __forceinline__ void mma_tf32_16n8k8(
    float& d0, float& d1, float& d2, float& d3,
    uint32_t a0, uint32_t a1, uint32_t a2, uint32_t a3,
    uint32_t b0, uint32_t b1)
{
    asm volatile(
        "mma.sync.aligned.m16n8k8.row.col.f32.tf32.tf32.f32 "
        "{%0,%1,%2,%3}, {%4,%5,%6,%7}, {%8,%9}, {%0,%1,%2,%3};"
        : "+f"(d0), "+f"(d1), "+f"(d2), "+f"(d3)
        : "r"(a0), "r"(a1), "r"(a2), "r"(a3), "r"(b0), "r"(b1));
}

// ---------------- LayerNorm (rounded-to-tf32 output) ---------------------
__global__ __launch_bounds__(256)
void layernorm_kernel(const float* __restrict__ x,
                      const float* __restrict__ gamma,
                      const float* __restrict__ beta,
                      float* __restrict__ out)
{
    const int row = blockIdx.x;
    const int tid = threadIdx.x;
    float4 v = ((const float4*)(x + (size_t)row * DD))[tid];

    float s  = v.x + v.y + v.z + v.w;
    float sq = v.x * v.x + v.y * v.y + v.z * v.z + v.w * v.w;
    __shared__ float ws[8], wq[8];
    #pragma unroll
    for (int o = 16; o; o >>= 1) {
        s  += __shfl_xor_sync(0xffffffffu, s,  o);
        sq += __shfl_xor_sync(0xffffffffu, sq, o);
    }
    const int w = tid >> 5, l = tid & 31;
    if (l == 0) { ws[w] = s; wq[w] = sq; }
    __syncthreads();
    if (w == 0) {
        s  = (l < 8) ? ws[l] : 0.f;
        sq = (l < 8) ? wq[l] : 0.f;
        #pragma unroll
        for (int o = 4; o; o >>= 1) {
            s  += __shfl_xor_sync(0xffffffffu, s,  o);
            sq += __shfl_xor_sync(0xffffffffu, sq, o);
        }
        if (l == 0) { ws[0] = s; wq[0] = sq; }
    }
    __syncthreads();
    const float mean = ws[0] * (1.f / (float)DD);
    const float var  = wq[0] * (1.f / (float)DD) - mean * mean;
    const float rstd = rsqrtf(var + 1e-5f);
    float4 g = ((const float4*)gamma)[tid];
    float4 b = ((const float4*)beta )[tid];
    float4 o4;
    o4.x = rna_tf32(g.x * ((v.x - mean) * rstd) + b.x);
    o4.y = rna_tf32(g.y * ((v.y - mean) * rstd) + b.y);
    o4.z = rna_tf32(g.z * ((v.z - mean) * rstd) + b.z);
    o4.w = rna_tf32(g.w * ((v.w - mean) * rstd) + b.w);
    ((float4*)(out + (size_t)row * DD))[tid] = o4;
}

// ---------------- causal softmax (rounded output, 128-pad zeroed) --------
__global__ __launch_bounds__(256)
void softmax_kernel(float* __restrict__ scores)
{
    const int row = blockIdx.x;
    const int b = row >> 11;
    const int i = row & (SS - 1);
    float* p = scores + (size_t)b * SS * SS + (size_t)i * SS;
    const int len = i + 1;
    const int tid = threadIdx.x;
    __shared__ float sh[8];

    float m = -1e30f;
    for (int j = tid; j < len; j += 256) m = fmaxf(m, p[j]);
    #pragma unroll
    for (int o = 16; o; o >>= 1) m = fmaxf(m, __shfl_xor_sync(0xffffffffu, m, o));
    const int w = tid >> 5, l = tid & 31;
    if (l == 0) sh[w] = m;
    __syncthreads();
    if (w == 0) {
        m = (l < 8) ? sh[l] : -1e30f;
        #pragma unroll
        for (int o = 4; o; o >>= 1) m = fmaxf(m, __shfl_xor_sync(0xffffffffu, m, o));
        if (l == 0) sh[0] = m;
    }
    __syncthreads();
    m = sh[0];
    __syncthreads();

    float sum = 0.f;
    for (int j = tid; j < len; j += 256) {
        float e = __expf(p[j] - m);
        p[j] = e;
        sum += e;
    }
    #pragma unroll
    for (int o = 16; o; o >>= 1) sum += __shfl_xor_sync(0xffffffffu, sum, o);
    if (l == 0) sh[w] = sum;
    __syncthreads();
    if (w == 0) {
        sum = (l < 8) ? sh[l] : 0.f;
        #pragma unroll
        for (int o = 4; o; o >>= 1) sum += __shfl_xor_sync(0xffffffffu, sum, o);
        if (l == 0) sh[0] = sum;
    }
    __syncthreads();
    const float inv = 1.f / sh[0];
    const int lenp = (len + 127) & ~127;
    for (int j = tid; j < lenp; j += 256)
        p[j] = (j < len) ? rna_tf32(p[j] * inv) : 0.f;
}

// ---------------- transpose (rounded): in[R,C] -> out[C,R] ----------------
__global__ __launch_bounds__(256)
void transpose_kernel(const float* __restrict__ in, float* __restrict__ out,
                      int R, int C)
{
    __shared__ float t[32][33];
    const int c0 = blockIdx.x * 32, r0 = blockIdx.y * 32;
    const int x = threadIdx.x, y = threadIdx.y;
    #pragma unroll
    for (int i = 0; i < 32; i += 8)
        t[y + i][x] = in[(size_t)(r0 + y + i) * C + c0 + x];
    __syncthreads();
    #pragma unroll
    for (int i = 0; i < 32; i += 8)
        out[(size_t)(c0 + y + i) * R + r0 + x] = rna_tf32(t[x][y + i]);
}

// ---------------- tf32 mma.sync GEMM: C[M,N] = A[M,K] * B[N,K]^T ----------
// CTA tile 128x128x32, 8 warps (4m x 2n), warp tile 32x64, double-buffered
// cp.async. SMEM row stride 36 floats -> bank = (4r+c)%32, conflict-free
// fragment loads. EPI: 0=none 1=alpha 2=bias+relu 3=bias+res 4=res.
#define BM 128
#define BN 128
#define BK 32
#define SST 36                         // smem row stride (floats)
static constexpr int TILE_BYTES = BM * SST * 4;        // 18432
static constexpr int OFF_B_S    = 2 * TILE_BYTES;      // A double buffer first
static constexpr int SMEM_TOT   = 4 * TILE_BYTES;      // 73728

template <int EPI, bool RND, bool CSKIP, bool KLIM>
__global__ __launch_bounds__(256)
void mma_gemm(const float* __restrict__ Ag, const float* __restrict__ Bg,
              float* __restrict__ Cg, const float* __restrict__ bias,
              const float* __restrict__ Rg,
              int K, int lda, int ldb, int ldc,
              long long sA, long long sB, long long sC, long long sR,
              float alpha)
{
    const int m0 = blockIdx.y * BM, n0 = blockIdx.x * BN, bz = blockIdx.z;
    if (CSKIP && n0 >= m0 + BM) return;
    Ag += (size_t)bz * sA;
    Bg += (size_t)bz * sB;
    Cg += (size_t)bz * sC;
    if (EPI == 3 || EPI == 4) Rg += (size_t)bz * sR;

    extern __shared__ char smem[];
    const uint32_t sb = smem_u32(smem);
    float* sf = (float*)smem;

    const int tid  = threadIdx.x;
    const int wid  = tid >> 5;
    const int lane = tid & 31;
    const int wm   = (wid >> 1) * 32;    // warp m offset (0,32,64,96)
    const int wn   = (wid & 1) * 64;     // warp n offset (0,64)
    const int lr   = lane >> 2;          // 0..7
    const int lc   = lane & 3;           // 0..3

    int kend = K;
    if (KLIM) { int lim = m0 + BM; kend = lim < K ? lim : K; }
    const int T = kend >> 5;

    float acc[2][8][4];
    #pragma unroll
    for (int mi = 0; mi < 2; mi++)
        #pragma unroll
        for (int ni = 0; ni < 8; ni++)
            #pragma unroll
            for (int q = 0; q < 4; q++) acc[mi][ni][q] = 0.f;

    // 128 rows x 8 float4-chunks = 1024 chunks per tile; 4 per thread
    auto cpA = [&](int t, int s) {
        const float* base = Ag + (size_t)m0 * lda + t * BK;
        const uint32_t db = sb + s * TILE_BYTES;
        #pragma unroll
        for (int it = 0; it < 4; it++) {
            const int idx = tid + it * 256;
            const int r = idx >> 3, c4 = idx & 7;
            cpa16(db + (uint32_t)(r * (SST * 4) + c4 * 16),
                  base + (size_t)r * lda + c4 * 4);
        }
    };
    auto cpB = [&](int t, int s) {
        const float* base = Bg + (size_t)n0 * ldb + t * BK;
        const uint32_t db = sb + OFF_B_S + s * TILE_BYTES;
        #pragma unroll
        for (int it = 0; it < 4; it++) {
            const int idx = tid + it * 256;
            const int r = idx >> 3, c4 = idx & 7;
            cpa16(db + (uint32_t)(r * (SST * 4) + c4 * 16),
                  base + (size_t)r * ldb + c4 * 4);
        }
    };

    cpA(0, 0); cpB(0, 0); cp_commit();

    for (int i = 0; i < T; i++) {
        const int b = i & 1;
        if (i + 1 < T) {
            cpA(i + 1, 1 - b); cpB(i + 1, 1 - b); cp_commit();
            cp_wait1();
        } else {
            cp_wait0();
        }
        __syncthreads();

        const float* sa = sf + (size_t)b * (TILE_BYTES / 4);
        const float* sbb = sf + (size_t)(OFF_B_S / 4) + (size_t)b * (TILE_BYTES / 4);

        #pragma unroll
        for (int ks = 0; ks < 4; ks++) {
            const int kb = ks * 8;
            uint32_t af[2][4];
            #pragma unroll
            for (int mi = 0; mi < 2; mi++) {
                const int r = wm + mi * 16 + lr;
                af[mi][0] = __float_as_uint(sa[(r    ) * SST + kb + lc    ]);
                af[mi][1] = __float_as_uint(sa[(r + 8) * SST + kb + lc    ]);
                af[mi][2] = __float_as_uint(sa[(r    ) * SST + kb + lc + 4]);
                af[mi][3] = __float_as_uint(sa[(r + 8) * SST + kb + lc + 4]);
            }
            uint32_t bf[8][2];
            #pragma unroll
            for (int ni = 0; ni < 8; ni++) {
                const int n = wn + ni * 8 + lr;
                bf[ni][0] = __float_as_uint(sbb[n * SST + kb + lc    ]);
                bf[ni][1] = __float_as_uint(sbb[n * SST + kb + lc + 4]);
            }
            #pragma unroll
            for (int mi = 0; mi < 2; mi++)
                #pragma unroll
                for (int ni = 0; ni < 8; ni++)
                    mma_tf32_16n8k8(acc[mi][ni][0], acc[mi][ni][1],
                                    acc[mi][ni][2], acc[mi][ni][3],
                                    af[mi][0], af[mi][1], af[mi][2], af[mi][3],
                                    bf[ni][0], bf[ni][1]);
        }
        __syncthreads();
    }

    // ---- epilogue: d0,d1 -> (row, col..col+1); d2,d3 -> (row+8, ...) ----
    #pragma unroll
    for (int mi = 0; mi < 2; mi++) {
        const int r0 = m0 + wm + mi * 16 + lr;
        #pragma unroll
        for (int ni = 0; ni < 8; ni++) {
            const int col = n0 + wn + ni * 8 + 2 * lc;
            #pragma unroll
            for (int h = 0; h < 2; h++) {
                const int r = r0 + h * 8;
                float vx = acc[mi][ni][2 * h + 0];
                float vy = acc[mi][ni][2 * h + 1];
                const size_t off = (size_t)r * ldc + col;
                if (EPI == 1) {
                    vx *= alpha; vy *= alpha;
                } else if (EPI == 2) {
                    vx = fmaxf(vx + __ldg(bias + col + 0), 0.f);
                    vy = fmaxf(vy + __ldg(bias + col + 1), 0.f);
                } else if (EPI == 3) {
                    float2 rr = *(const float2*)(Rg + off);
                    vx += __ldg(bias + col + 0) + rr.x;
                    vy += __ldg(bias + col + 1) + rr.y;
                } else if (EPI == 4) {
                    float2 rr = *(const float2*)(Rg + off);
                    vx += rr.x; vy += rr.y;
                }
                if (RND) { vx = rna_tf32(vx); vy = rna_tf32(vy); }
                float2 o2; o2.x = vx; o2.y = vy;
                *(float2*)(Cg + off) = o2;
            }
        }
    }
}

// ---------------- launcher ------------------------------------------------
extern "C" void kernel_launch(void* const* d_in, const int* in_sizes, int n_in,
                              void* d_out, int out_size)
{
    (void)in_sizes; (void)n_in; (void)out_size;
    const float* x      = (const float*)d_in[0];
    const float* Qw     = (const float*)d_in[1];
    const float* Kw     = (const float*)d_in[2];
    const float* Vw     = (const float*)d_in[3];
    const float* w1     = (const float*)d_in[4];
    const float* b1     = (const float*)d_in[5];
    const float* w2     = (const float*)d_in[6];
    const float* b2     = (const float*)d_in[7];
    const float* gamma1 = (const float*)d_in[8];
    const float* beta1  = (const float*)d_in[9];
    const float* gamma2 = (const float*)d_in[10];
    const float* beta2  = (const float*)d_in[11];
    float* out = (float*)d_out;

    float *pln1, *pQ, *pK, *pVt, *pS, *px1, *pln2, *pH;
    float *pQwt, *pKwt, *pVwt, *pw1t, *pw2t;
    cudaGetSymbolAddress((void**)&pln1, g_ln1);
    cudaGetSymbolAddress((void**)&pQ,   g_Q);
    cudaGetSymbolAddress((void**)&pK,   g_K);
    cudaGetSymbolAddress((void**)&pVt,  g_Vt);
    cudaGetSymbolAddress((void**)&pS,   g_S);
    cudaGetSymbolAddress((void**)&px1,  g_x1);
    cudaGetSymbolAddress((void**)&pln2, g_ln2);
    cudaGetSymbolAddress((void**)&pH,   g_H);
    cudaGetSymbolAddress((void**)&pQwt, g_Qwt);
    cudaGetSymbolAddress((void**)&pKwt, g_Kwt);
    cudaGetSymbolAddress((void**)&pVwt, g_Vwt);
    cudaGetSymbolAddress((void**)&pw1t, g_w1t);
    cudaGetSymbolAddress((void**)&pw2t, g_w2t);

    cudaFuncSetAttribute(mma_gemm<0, true,  false, false>,
        cudaFuncAttributeMaxDynamicSharedMemorySize, SMEM_TOT);
    cudaFuncSetAttribute(mma_gemm<1, false, true,  false>,
        cudaFuncAttributeMaxDynamicSharedMemorySize, SMEM_TOT);
    cudaFuncSetAttribute(mma_gemm<4, false, false, true>,
        cudaFuncAttributeMaxDynamicSharedMemorySize, SMEM_TOT);
    cudaFuncSetAttribute(mma_gemm<2, true,  false, false>,
        cudaFuncAttributeMaxDynamicSharedMemorySize, SMEM_TOT);
    cudaFuncSetAttribute(mma_gemm<3, false, false, false>,
        cudaFuncAttributeMaxDynamicSharedMemorySize, SMEM_TOT);

    const int MR = BB * SS;                 // 8192
    const long long SD  = (long long)SS * DD;
    const long long SSq = (long long)SS * SS;
    const long long DS  = (long long)DD * SS;
    dim3 tb(32, 8);

    // 0) weight transposes (K-major B operands), rounded to tf32
    transpose_kernel<<<dim3(DD / 32, DD / 32), tb>>>(Qw, pQwt, DD, DD);
    transpose_kernel<<<dim3(DD / 32, DD / 32), tb>>>(Kw, pKwt, DD, DD);
    transpose_kernel<<<dim3(DD / 32, DD / 32), tb>>>(Vw, pVwt, DD, DD);
    transpose_kernel<<<dim3(FF / 32, DD / 32), tb>>>(w1, pw1t, DD, FF);
    transpose_kernel<<<dim3(DD / 32, FF / 32), tb>>>(w2, pw2t, FF, DD);

    // 1) LN1
    layernorm_kernel<<<MR, 256>>>(x, gamma1, beta1, pln1);

    // 2) Q = ln1 @ Qw ; K = ln1 @ Kw   (M=8192, N=1024, K=1024)
    dim3 gq(DD / BN, MR / BM, 1);
    mma_gemm<0, true, false, false><<<gq, 256, SMEM_TOT>>>(
        pln1, pQwt, pQ, nullptr, nullptr, DD, DD, DD, DD, 0, 0, 0, 0, 1.f);
    mma_gemm<0, true, false, false><<<gq, 256, SMEM_TOT>>>(
        pln1, pKwt, pK, nullptr, nullptr, DD, DD, DD, DD, 0, 0, 0, 0, 1.f);

    // 3) Vt[b,d,s] = sum_k Vwt[d,k] * ln1[b,s,k]   (M=1024, N=2048 per batch)
    dim3 gv(SS / BN, DD / BM, BB);
    mma_gemm<0, true, false, false><<<gv, 256, SMEM_TOT>>>(
        pVwt, pln1, pVt, nullptr, nullptr, DD, DD, DD, SS, 0, SD, DS, 0, 1.f);

    // 4) scores = Q @ K^T / 32, causal tiles only  (M=N=2048, K=1024)
    dim3 gs(SS / BN, SS / BM, BB);
    mma_gemm<1, false, true, false><<<gs, 256, SMEM_TOT>>>(
        pQ, pK, pS, nullptr, nullptr, DD, DD, DD, SS, SD, SD, SSq, 0, 0.03125f);

    // 5) causal softmax (rounded, zero-padded to 128 boundary)
    softmax_kernel<<<MR, 256>>>(pS);

    // 6) x1 = P @ V + x    (M=2048, N=1024, K<=row band, per batch)
    dim3 gp(DD / BN, SS / BM, BB);
    mma_gemm<4, false, false, true><<<gp, 256, SMEM_TOT>>>(
        pS, pVt, px1, nullptr, x, SS, SS, SS, DD, SSq, DS, SD, SD, 1.f);

    // 7) LN2
    layernorm_kernel<<<MR, 256>>>(px1, gamma2, beta2, pln2);

    // 8) H = relu(ln2 @ w1 + b1)   (M=8192, N=4096, K=1024)
    dim3 g1(FF / BN, MR / BM, 1);
    mma_gemm<2, true, false, false><<<g1, 256, SMEM_TOT>>>(
        pln2, pw1t, pH, b1, nullptr, DD, DD, DD, FF, 0, 0, 0, 0, 1.f);

    // 9) out = H @ w2 + b2 + x1    (M=8192, N=1024, K=4096)
    dim3 g2(DD / BN, MR / BM, 1);
    mma_gemm<3, false, false, false><<<g2, 256, SMEM_TOT>>>(
        pH, pw2t, out, b2, px1, FF, FF, FF, DD, 0, 0, 0, 0, 1.f);
}

// round 8
// speedup vs baseline: 4.0611x; 1.1781x over previous
#include <cuda_runtime.h>
#include <cstdint>
#include <math.h>

#define BB 4
#define SS 2048
#define DD 1024
#define FF 4096

// ---------------- scratch (__device__ globals; no allocs allowed) --------
__device__ float g_ln1[(size_t)BB * SS * DD];
__device__ float g_Q  [(size_t)BB * SS * DD];
__device__ float g_K  [(size_t)BB * SS * DD];
__device__ float g_Vt [(size_t)BB * DD * SS];   // V transposed: [b][d][s]
__device__ float g_S  [(size_t)BB * SS * SS];
__device__ float g_x1 [(size_t)BB * SS * DD];
__device__ float g_ln2[(size_t)BB * SS * DD];
__device__ float g_H  [(size_t)BB * SS * FF];
__device__ float g_Qwt[(size_t)DD * DD];
__device__ float g_Kwt[(size_t)DD * DD];
__device__ float g_Vwt[(size_t)DD * DD];
__device__ float g_w1t[(size_t)DD * FF];
__device__ float g_w2t[(size_t)DD * FF];

// ---------------- helpers -------------------------------------------------
__device__ __forceinline__ uint32_t smem_u32(const void* p) {
    uint32_t a;
    asm("{ .reg .u64 t; cvta.to.shared.u64 t, %1; cvt.u32.u64 %0, t; }"
        : "=r"(a) : "l"(p));
    return a;
}
__device__ __forceinline__ float rna_tf32(float x) {
    uint32_t u;
    asm("cvt.rna.tf32.f32 %0, %1;" : "=r"(u) : "f"(x));
    return __uint_as_float(u);
}
__device__ __forceinline__ void cpa16(uint32_t dst, const void* src) {
    asm volatile("cp.async.cg.shared.global [%0], [%1], 16;\n"
                 :: "r"(dst), "l"(src));
}
__device__ __forceinline__ void cp_commit() {
    asm volatile("cp.async.commit_group;\n" ::: "memory");
}
__device__ __forceinline__ void cp_wait1() {
    asm volatile("cp.async.wait_group 1;\n" ::: "memory");
}
__device__ __forceinline__ void cp_wait0() {
    asm volatile("cp.async.wait_group 0;\n" ::: "memory");
}
__device__ __forceinline__ void mma_tf32_16n8k8(
    float& d0, float& d1, float& d2, float& d3,
    uint32_t a0, uint32_t a1, uint32_t a2, uint32_t a3,
    uint32_t b0, uint32_t b1)
{
    asm volatile(
        "mma.sync.aligned.m16n8k8.row.col.f32.tf32.tf32.f32 "
        "{%0,%1,%2,%3}, {%4,%5,%6,%7}, {%8,%9}, {%0,%1,%2,%3};"
        : "+f"(d0), "+f"(d1), "+f"(d2), "+f"(d3)
        : "r"(a0), "r"(a1), "r"(a2), "r"(a3), "r"(b0), "r"(b1));
}

// ---------------- LayerNorm (rounded-to-tf32 output) ---------------------
__global__ __launch_bounds__(256)
void layernorm_kernel(const float* __restrict__ x,
                      const float* __restrict__ gamma,
                      const float* __restrict__ beta,
                      float* __restrict__ out)
{
    const int row = blockIdx.x;
    const int tid = threadIdx.x;
    float4 v = ((const float4*)(x + (size_t)row * DD))[tid];

    float s  = v.x + v.y + v.z + v.w;
    float sq = v.x * v.x + v.y * v.y + v.z * v.z + v.w * v.w;
    __shared__ float ws[8], wq[8];
    #pragma unroll
    for (int o = 16; o; o >>= 1) {
        s  += __shfl_xor_sync(0xffffffffu, s,  o);
        sq += __shfl_xor_sync(0xffffffffu, sq, o);
    }
    const int w = tid >> 5, l = tid & 31;
    if (l == 0) { ws[w] = s; wq[w] = sq; }
    __syncthreads();
    if (w == 0) {
        s  = (l < 8) ? ws[l] : 0.f;
        sq = (l < 8) ? wq[l] : 0.f;
        #pragma unroll
        for (int o = 4; o; o >>= 1) {
            s  += __shfl_xor_sync(0xffffffffu, s,  o);
            sq += __shfl_xor_sync(0xffffffffu, sq, o);
        }
        if (l == 0) { ws[0] = s; wq[0] = sq; }
    }
    __syncthreads();
    const float mean = ws[0] * (1.f / (float)DD);
    const float var  = wq[0] * (1.f / (float)DD) - mean * mean;
    const float rstd = rsqrtf(var + 1e-5f);
    float4 g = ((const float4*)gamma)[tid];
    float4 b = ((const float4*)beta )[tid];
    float4 o4;
    o4.x = rna_tf32(g.x * ((v.x - mean) * rstd) + b.x);
    o4.y = rna_tf32(g.y * ((v.y - mean) * rstd) + b.y);
    o4.z = rna_tf32(g.z * ((v.z - mean) * rstd) + b.z);
    o4.w = rna_tf32(g.w * ((v.w - mean) * rstd) + b.w);
    ((float4*)(out + (size_t)row * DD))[tid] = o4;
}

// ---------------- causal softmax (rounded output, 128-pad zeroed) --------
__global__ __launch_bounds__(256)
void softmax_kernel(float* __restrict__ scores)
{
    const int row = blockIdx.x;
    const int b = row >> 11;
    const int i = row & (SS - 1);
    float* p = scores + (size_t)b * SS * SS + (size_t)i * SS;
    const int len = i + 1;
    const int tid = threadIdx.x;
    __shared__ float sh[8];

    float m = -1e30f;
    for (int j = tid; j < len; j += 256) m = fmaxf(m, p[j]);
    #pragma unroll
    for (int o = 16; o; o >>= 1) m = fmaxf(m, __shfl_xor_sync(0xffffffffu, m, o));
    const int w = tid >> 5, l = tid & 31;
    if (l == 0) sh[w] = m;
    __syncthreads();
    if (w == 0) {
        m = (l < 8) ? sh[l] : -1e30f;
        #pragma unroll
        for (int o = 4; o; o >>= 1) m = fmaxf(m, __shfl_xor_sync(0xffffffffu, m, o));
        if (l == 0) sh[0] = m;
    }
    __syncthreads();
    m = sh[0];
    __syncthreads();

    float sum = 0.f;
    for (int j = tid; j < len; j += 256) {
        float e = __expf(p[j] - m);
        p[j] = e;
        sum += e;
    }
    #pragma unroll
    for (int o = 16; o; o >>= 1) sum += __shfl_xor_sync(0xffffffffu, sum, o);
    if (l == 0) sh[w] = sum;
    __syncthreads();
    if (w == 0) {
        sum = (l < 8) ? sh[l] : 0.f;
        #pragma unroll
        for (int o = 4; o; o >>= 1) sum += __shfl_xor_sync(0xffffffffu, sum, o);
        if (l == 0) sh[0] = sum;
    }
    __syncthreads();
    const float inv = 1.f / sh[0];
    const int lenp = (len + 127) & ~127;
    for (int j = tid; j < lenp; j += 256)
        p[j] = (j < len) ? rna_tf32(p[j] * inv) : 0.f;
}

// ---------------- transpose (rounded): in[R,C] -> out[C,R] ----------------
__global__ __launch_bounds__(256)
void transpose_kernel(const float* __restrict__ in, float* __restrict__ out,
                      int R, int C)
{
    __shared__ float t[32][33];
    const int c0 = blockIdx.x * 32, r0 = blockIdx.y * 32;
    const int x = threadIdx.x, y = threadIdx.y;
    #pragma unroll
    for (int i = 0; i < 32; i += 8)
        t[y + i][x] = in[(size_t)(r0 + y + i) * C + c0 + x];
    __syncthreads();
    #pragma unroll
    for (int i = 0; i < 32; i += 8)
        out[(size_t)(c0 + y + i) * R + r0 + x] = rna_tf32(t[x][y + i]);
}

// ---------------- tf32 mma.sync GEMM: C[M,N] = A[M,K] * B[N,K]^T ----------
// CTA tile 128x128x32, 4 warps (2m x 2n), warp tile 64x64, 3-stage cp.async
// pipeline. SMEM row stride 36 floats -> bank = (4r+c)%32, conflict-free.
// EPI: 0=none 1=alpha 2=bias+relu 3=bias+res 4=res.
#define BM 128
#define BN 128
#define BK 32
#define SST 36                          // smem row stride (floats)
static constexpr int TILE_BYTES  = BM * SST * 4;          // 18432
static constexpr int STAGE_BYTES = 2 * TILE_BYTES;        // A + B = 36864
static constexpr int NSTAGE      = 3;
static constexpr int SMEM_TOT    = NSTAGE * STAGE_BYTES;  // 110592

template <int EPI, bool RND, bool CSKIP, bool KLIM>
__global__ __launch_bounds__(128)
void mma_gemm(const float* __restrict__ Ag, const float* __restrict__ Bg,
              float* __restrict__ Cg, const float* __restrict__ bias,
              const float* __restrict__ Rg,
              int K, int lda, int ldb, int ldc,
              long long sA, long long sB, long long sC, long long sR,
              float alpha)
{
    const int m0 = blockIdx.y * BM, n0 = blockIdx.x * BN, bz = blockIdx.z;
    if (CSKIP && n0 >= m0 + BM) return;
    Ag += (size_t)bz * sA;
    Bg += (size_t)bz * sB;
    Cg += (size_t)bz * sC;
    if (EPI == 3 || EPI == 4) Rg += (size_t)bz * sR;

    extern __shared__ char smem[];
    const uint32_t sb = smem_u32(smem);
    float* sf = (float*)smem;

    const int tid  = threadIdx.x;
    const int wid  = tid >> 5;
    const int lane = tid & 31;
    const int wm   = (wid >> 1) * 64;    // warp m offset (0,64)
    const int wn   = (wid & 1) * 64;     // warp n offset (0,64)
    const int lr   = lane >> 2;          // 0..7
    const int lc   = lane & 3;           // 0..3

    int kend = K;
    if (KLIM) { int lim = m0 + BM; kend = lim < K ? lim : K; }
    const int T = kend >> 5;

    float acc[4][8][4];
    #pragma unroll
    for (int mi = 0; mi < 4; mi++)
        #pragma unroll
        for (int ni = 0; ni < 8; ni++)
            #pragma unroll
            for (int q = 0; q < 4; q++) acc[mi][ni][q] = 0.f;

    // 128 rows x 8 float4-chunks = 1024 chunks per operand tile; 8/thread
    auto cpA = [&](int t, int slot) {
        const float* base = Ag + (size_t)m0 * lda + t * BK;
        const uint32_t db = sb + slot * STAGE_BYTES;
        #pragma unroll
        for (int it = 0; it < 8; it++) {
            const int idx = tid + it * 128;
            const int r = idx >> 3, c4 = idx & 7;
            cpa16(db + (uint32_t)(r * (SST * 4) + c4 * 16),
                  base + (size_t)r * lda + c4 * 4);
        }
    };
    auto cpB = [&](int t, int slot) {
        const float* base = Bg + (size_t)n0 * ldb + t * BK;
        const uint32_t db = sb + slot * STAGE_BYTES + TILE_BYTES;
        #pragma unroll
        for (int it = 0; it < 8; it++) {
            const int idx = tid + it * 128;
            const int r = idx >> 3, c4 = idx & 7;
            cpa16(db + (uint32_t)(r * (SST * 4) + c4 * 16),
                  base + (size_t)r * ldb + c4 * 4);
        }
    };

    // prologue: stages 0 and 1, separate commit groups
    cpA(0, 0); cpB(0, 0); cp_commit();
    if (T > 1) { cpA(1, 1); cpB(1, 1); cp_commit(); }

    int slot = 0;
    for (int i = 0; i < T; i++) {
        if (i < T - 1) cp_wait1(); else cp_wait0();
        __syncthreads();

        const float* sa  = sf + (size_t)slot * (STAGE_BYTES / 4);
        const float* sbb = sa + (TILE_BYTES / 4);

        #pragma unroll
        for (int ks = 0; ks < 4; ks++) {
            const int kb = ks * 8;
            uint32_t af[4][4];
            #pragma unroll
            for (int mi = 0; mi < 4; mi++) {
                const int r = wm + mi * 16 + lr;
                af[mi][0] = __float_as_uint(sa[(r    ) * SST + kb + lc    ]);
                af[mi][1] = __float_as_uint(sa[(r + 8) * SST + kb + lc    ]);
                af[mi][2] = __float_as_uint(sa[(r    ) * SST + kb + lc + 4]);
                af[mi][3] = __float_as_uint(sa[(r + 8) * SST + kb + lc + 4]);
            }
            uint32_t bf[8][2];
            #pragma unroll
            for (int ni = 0; ni < 8; ni++) {
                const int n = wn + ni * 8 + lr;
                bf[ni][0] = __float_as_uint(sbb[n * SST + kb + lc    ]);
                bf[ni][1] = __float_as_uint(sbb[n * SST + kb + lc + 4]);
            }
            #pragma unroll
            for (int mi = 0; mi < 4; mi++)
                #pragma unroll
                for (int ni = 0; ni < 8; ni++)
                    mma_tf32_16n8k8(acc[mi][ni][0], acc[mi][ni][1],
                                    acc[mi][ni][2], acc[mi][ni][3],
                                    af[mi][0], af[mi][1], af[mi][2], af[mi][3],
                                    bf[ni][0], bf[ni][1]);
        }

        // prefetch stage i+2 into the slot freed by iteration i-1
        if (i + 2 < T) {
            const int ns = (slot + 2) % NSTAGE;
            cpA(i + 2, ns); cpB(i + 2, ns); cp_commit();
        }
        slot = (slot + 1) % NSTAGE;
    }

    // ---- epilogue: d0,d1 -> (row, col..col+1); d2,d3 -> (row+8, ...) ----
    #pragma unroll
    for (int mi = 0; mi < 4; mi++) {
        const int r0 = m0 + wm + mi * 16 + lr;
        #pragma unroll
        for (int ni = 0; ni < 8; ni++) {
            const int col = n0 + wn + ni * 8 + 2 * lc;
            #pragma unroll
            for (int h = 0; h < 2; h++) {
                const int r = r0 + h * 8;
                float vx = acc[mi][ni][2 * h + 0];
                float vy = acc[mi][ni][2 * h + 1];
                const size_t off = (size_t)r * ldc + col;
                if (EPI == 1) {
                    vx *= alpha; vy *= alpha;
                } else if (EPI == 2) {
                    vx = fmaxf(vx + __ldg(bias + col + 0), 0.f);
                    vy = fmaxf(vy + __ldg(bias + col + 1), 0.f);
                } else if (EPI == 3) {
                    float2 rr = *(const float2*)(Rg + off);
                    vx += __ldg(bias + col + 0) + rr.x;
                    vy += __ldg(bias + col + 1) + rr.y;
                } else if (EPI == 4) {
                    float2 rr = *(const float2*)(Rg + off);
                    vx += rr.x; vy += rr.y;
                }
                if (RND) { vx = rna_tf32(vx); vy = rna_tf32(vy); }
                float2 o2; o2.x = vx; o2.y = vy;
                *(float2*)(Cg + off) = o2;
            }
        }
    }
}

// ---------------- launcher ------------------------------------------------
extern "C" void kernel_launch(void* const* d_in, const int* in_sizes, int n_in,
                              void* d_out, int out_size)
{
    (void)in_sizes; (void)n_in; (void)out_size;
    const float* x      = (const float*)d_in[0];
    const float* Qw     = (const float*)d_in[1];
    const float* Kw     = (const float*)d_in[2];
    const float* Vw     = (const float*)d_in[3];
    const float* w1     = (const float*)d_in[4];
    const float* b1     = (const float*)d_in[5];
    const float* w2     = (const float*)d_in[6];
    const float* b2     = (const float*)d_in[7];
    const float* gamma1 = (const float*)d_in[8];
    const float* beta1  = (const float*)d_in[9];
    const float* gamma2 = (const float*)d_in[10];
    const float* beta2  = (const float*)d_in[11];
    float* out = (float*)d_out;

    float *pln1, *pQ, *pK, *pVt, *pS, *px1, *pln2, *pH;
    float *pQwt, *pKwt, *pVwt, *pw1t, *pw2t;
    cudaGetSymbolAddress((void**)&pln1, g_ln1);
    cudaGetSymbolAddress((void**)&pQ,   g_Q);
    cudaGetSymbolAddress((void**)&pK,   g_K);
    cudaGetSymbolAddress((void**)&pVt,  g_Vt);
    cudaGetSymbolAddress((void**)&pS,   g_S);
    cudaGetSymbolAddress((void**)&px1,  g_x1);
    cudaGetSymbolAddress((void**)&pln2, g_ln2);
    cudaGetSymbolAddress((void**)&pH,   g_H);
    cudaGetSymbolAddress((void**)&pQwt, g_Qwt);
    cudaGetSymbolAddress((void**)&pKwt, g_Kwt);
    cudaGetSymbolAddress((void**)&pVwt, g_Vwt);
    cudaGetSymbolAddress((void**)&pw1t, g_w1t);
    cudaGetSymbolAddress((void**)&pw2t, g_w2t);

    cudaFuncSetAttribute(mma_gemm<0, true,  false, false>,
        cudaFuncAttributeMaxDynamicSharedMemorySize, SMEM_TOT);
    cudaFuncSetAttribute(mma_gemm<1, false, true,  false>,
        cudaFuncAttributeMaxDynamicSharedMemorySize, SMEM_TOT);
    cudaFuncSetAttribute(mma_gemm<4, false, false, true>,
        cudaFuncAttributeMaxDynamicSharedMemorySize, SMEM_TOT);
    cudaFuncSetAttribute(mma_gemm<2, true,  false, false>,
        cudaFuncAttributeMaxDynamicSharedMemorySize, SMEM_TOT);
    cudaFuncSetAttribute(mma_gemm<3, false, false, false>,
        cudaFuncAttributeMaxDynamicSharedMemorySize, SMEM_TOT);

    const int MR = BB * SS;                 // 8192
    const long long SD  = (long long)SS * DD;
    const long long SSq = (long long)SS * SS;
    const long long DS  = (long long)DD * SS;
    dim3 tb(32, 8);

    // 0) weight transposes (K-major B operands), rounded to tf32
    transpose_kernel<<<dim3(DD / 32, DD / 32), tb>>>(Qw, pQwt, DD, DD);
    transpose_kernel<<<dim3(DD / 32, DD / 32), tb>>>(Kw, pKwt, DD, DD);
    transpose_kernel<<<dim3(DD / 32, DD / 32), tb>>>(Vw, pVwt, DD, DD);
    transpose_kernel<<<dim3(FF / 32, DD / 32), tb>>>(w1, pw1t, DD, FF);
    transpose_kernel<<<dim3(DD / 32, FF / 32), tb>>>(w2, pw2t, FF, DD);

    // 1) LN1
    layernorm_kernel<<<MR, 256>>>(x, gamma1, beta1, pln1);

    // 2) Q = ln1 @ Qw ; K = ln1 @ Kw   (M=8192, N=1024, K=1024)
    dim3 gq(DD / BN, MR / BM, 1);
    mma_gemm<0, true, false, false><<<gq, 128, SMEM_TOT>>>(
        pln1, pQwt, pQ, nullptr, nullptr, DD, DD, DD, DD, 0, 0, 0, 0, 1.f);
    mma_gemm<0, true, false, false><<<gq, 128, SMEM_TOT>>>(
        pln1, pKwt, pK, nullptr, nullptr, DD, DD, DD, DD, 0, 0, 0, 0, 1.f);

    // 3) Vt[b,d,s] = sum_k Vwt[d,k] * ln1[b,s,k]   (M=1024, N=2048 per batch)
    dim3 gv(SS / BN, DD / BM, BB);
    mma_gemm<0, true, false, false><<<gv, 128, SMEM_TOT>>>(
        pVwt, pln1, pVt, nullptr, nullptr, DD, DD, DD, SS, 0, SD, DS, 0, 1.f);

    // 4) scores = Q @ K^T / 32, causal tiles only  (M=N=2048, K=1024)
    dim3 gs(SS / BN, SS / BM, BB);
    mma_gemm<1, false, true, false><<<gs, 128, SMEM_TOT>>>(
        pQ, pK, pS, nullptr, nullptr, DD, DD, DD, SS, SD, SD, SSq, 0, 0.03125f);

    // 5) causal softmax (rounded, zero-padded to 128 boundary)
    softmax_kernel<<<MR, 256>>>(pS);

    // 6) x1 = P @ V + x    (M=2048, N=1024, K<=row band, per batch)
    dim3 gp(DD / BN, SS / BM, BB);
    mma_gemm<4, false, false, true><<<gp, 128, SMEM_TOT>>>(
        pS, pVt, px1, nullptr, x, SS, SS, SS, DD, SSq, DS, SD, SD, 1.f);

    // 7) LN2
    layernorm_kernel<<<MR, 256>>>(px1, gamma2, beta2, pln2);

    // 8) H = relu(ln2 @ w1 + b1)   (M=8192, N=4096, K=1024)
    dim3 g1(FF / BN, MR / BM, 1);
    mma_gemm<2, true, false, false><<<g1, 128, SMEM_TOT>>>(
        pln2, pw1t, pH, b1, nullptr, DD, DD, DD, FF, 0, 0, 0, 0, 1.f);

    // 9) out = H @ w2 + b2 + x1    (M=8192, N=1024, K=4096)
    dim3 g2(DD / BN, MR / BM, 1);
    mma_gemm<3, false, false, false><<<g2, 128, SMEM_TOT>>>(
        pH, pw2t, out, b2, px1, FF, FF, FF, DD, 0, 0, 0, 0, 1.f);
}

// round 9
// speedup vs baseline: 4.1586x; 1.0240x over previous
#include <cuda_runtime.h>
#include <cstdint>
#include <math.h>

#define BB 4
#define SS 2048
#define DD 1024
#define FF 4096

// ---------------- scratch (__device__ globals; no allocs allowed) --------
__device__ float g_ln1[(size_t)BB * SS * DD];
__device__ float g_Q  [(size_t)BB * SS * DD];
__device__ float g_K  [(size_t)BB * SS * DD];
__device__ float g_Vt [(size_t)BB * DD * SS];   // V transposed: [b][d][s]
__device__ float g_S  [(size_t)BB * SS * SS];
__device__ float g_x1 [(size_t)BB * SS * DD];
__device__ float g_ln2[(size_t)BB * SS * DD];
__device__ float g_H  [(size_t)BB * SS * FF];
__device__ float g_Qwt[(size_t)DD * DD];
__device__ float g_Kwt[(size_t)DD * DD];
__device__ float g_Vwt[(size_t)DD * DD];
__device__ float g_w1t[(size_t)DD * FF];
__device__ float g_w2t[(size_t)DD * FF];

// ---------------- helpers -------------------------------------------------
__device__ __forceinline__ uint32_t smem_u32(const void* p) {
    uint32_t a;
    asm("{ .reg .u64 t; cvta.to.shared.u64 t, %1; cvt.u32.u64 %0, t; }"
        : "=r"(a) : "l"(p));
    return a;
}
__device__ __forceinline__ float rna_tf32(float x) {
    uint32_t u;
    asm("cvt.rna.tf32.f32 %0, %1;" : "=r"(u) : "f"(x));
    return __uint_as_float(u);
}
__device__ __forceinline__ void cpa16(uint32_t dst, const void* src) {
    asm volatile("cp.async.cg.shared.global [%0], [%1], 16;\n"
                 :: "r"(dst), "l"(src));
}
__device__ __forceinline__ void cp_commit() {
    asm volatile("cp.async.commit_group;\n" ::: "memory");
}
__device__ __forceinline__ void cp_wait1() {
    asm volatile("cp.async.wait_group 1;\n" ::: "memory");
}
__device__ __forceinline__ void cp_wait0() {
    asm volatile("cp.async.wait_group 0;\n" ::: "memory");
}
__device__ __forceinline__ void mma_tf32_16n8k8(
    float& d0, float& d1, float& d2, float& d3,
    uint32_t a0, uint32_t a1, uint32_t a2, uint32_t a3,
    uint32_t b0, uint32_t b1)
{
    asm volatile(
        "mma.sync.aligned.m16n8k8.row.col.f32.tf32.tf32.f32 "
        "{%0,%1,%2,%3}, {%4,%5,%6,%7}, {%8,%9}, {%0,%1,%2,%3};"
        : "+f"(d0), "+f"(d1), "+f"(d2), "+f"(d3)
        : "r"(a0), "r"(a1), "r"(a2), "r"(a3), "r"(b0), "r"(b1));
}

// ---------------- LayerNorm (rounded-to-tf32 output) ---------------------
__global__ __launch_bounds__(256)
void layernorm_kernel(const float* __restrict__ x,
                      const float* __restrict__ gamma,
                      const float* __restrict__ beta,
                      float* __restrict__ out)
{
    const int row = blockIdx.x;
    const int tid = threadIdx.x;
    float4 v = ((const float4*)(x + (size_t)row * DD))[tid];

    float s  = v.x + v.y + v.z + v.w;
    float sq = v.x * v.x + v.y * v.y + v.z * v.z + v.w * v.w;
    __shared__ float ws[8], wq[8];
    #pragma unroll
    for (int o = 16; o; o >>= 1) {
        s  += __shfl_xor_sync(0xffffffffu, s,  o);
        sq += __shfl_xor_sync(0xffffffffu, sq, o);
    }
    const int w = tid >> 5, l = tid & 31;
    if (l == 0) { ws[w] = s; wq[w] = sq; }
    __syncthreads();
    if (w == 0) {
        s  = (l < 8) ? ws[l] : 0.f;
        sq = (l < 8) ? wq[l] : 0.f;
        #pragma unroll
        for (int o = 4; o; o >>= 1) {
            s  += __shfl_xor_sync(0xffffffffu, s,  o);
            sq += __shfl_xor_sync(0xffffffffu, sq, o);
        }
        if (l == 0) { ws[0] = s; wq[0] = sq; }
    }
    __syncthreads();
    const float mean = ws[0] * (1.f / (float)DD);
    const float var  = wq[0] * (1.f / (float)DD) - mean * mean;
    const float rstd = rsqrtf(var + 1e-5f);
    float4 g = ((const float4*)gamma)[tid];
    float4 b = ((const float4*)beta )[tid];
    float4 o4;
    o4.x = rna_tf32(g.x * ((v.x - mean) * rstd) + b.x);
    o4.y = rna_tf32(g.y * ((v.y - mean) * rstd) + b.y);
    o4.z = rna_tf32(g.z * ((v.z - mean) * rstd) + b.z);
    o4.w = rna_tf32(g.w * ((v.w - mean) * rstd) + b.w);
    ((float4*)(out + (size_t)row * DD))[tid] = o4;
}

// ---------------- causal softmax (rounded output, 256-pad zeroed) --------
__global__ __launch_bounds__(256)
void softmax_kernel(float* __restrict__ scores)
{
    const int row = blockIdx.x;
    const int b = row >> 11;
    const int i = row & (SS - 1);
    float* p = scores + (size_t)b * SS * SS + (size_t)i * SS;
    const int len = i + 1;
    const int tid = threadIdx.x;
    __shared__ float sh[8];

    float m = -1e30f;
    for (int j = tid; j < len; j += 256) m = fmaxf(m, p[j]);
    #pragma unroll
    for (int o = 16; o; o >>= 1) m = fmaxf(m, __shfl_xor_sync(0xffffffffu, m, o));
    const int w = tid >> 5, l = tid & 31;
    if (l == 0) sh[w] = m;
    __syncthreads();
    if (w == 0) {
        m = (l < 8) ? sh[l] : -1e30f;
        #pragma unroll
        for (int o = 4; o; o >>= 1) m = fmaxf(m, __shfl_xor_sync(0xffffffffu, m, o));
        if (l == 0) sh[0] = m;
    }
    __syncthreads();
    m = sh[0];
    __syncthreads();

    float sum = 0.f;
    for (int j = tid; j < len; j += 256) {
        float e = __expf(p[j] - m);
        p[j] = e;
        sum += e;
    }
    #pragma unroll
    for (int o = 16; o; o >>= 1) sum += __shfl_xor_sync(0xffffffffu, sum, o);
    if (l == 0) sh[w] = sum;
    __syncthreads();
    if (w == 0) {
        sum = (l < 8) ? sh[l] : 0.f;
        #pragma unroll
        for (int o = 4; o; o >>= 1) sum += __shfl_xor_sync(0xffffffffu, sum, o);
        if (l == 0) sh[0] = sum;
    }
    __syncthreads();
    const float inv = 1.f / sh[0];
    // zero-pad to the 256 boundary: the K-limited P@V GEMM (BM=256) reads
    // k < m0+256 for every row of its tile.
    const int lenp = (len + 255) & ~255;
    for (int j = tid; j < lenp; j += 256)
        p[j] = (j < len) ? rna_tf32(p[j] * inv) : 0.f;
}

// ---------------- transpose (rounded): in[R,C] -> out[C,R] ----------------
__global__ __launch_bounds__(256)
void transpose_kernel(const float* __restrict__ in, float* __restrict__ out,
                      int R, int C)
{
    __shared__ float t[32][33];
    const int c0 = blockIdx.x * 32, r0 = blockIdx.y * 32;
    const int x = threadIdx.x, y = threadIdx.y;
    #pragma unroll
    for (int i = 0; i < 32; i += 8)
        t[y + i][x] = in[(size_t)(r0 + y + i) * C + c0 + x];
    __syncthreads();
    #pragma unroll
    for (int i = 0; i < 32; i += 8)
        out[(size_t)(c0 + y + i) * R + r0 + x] = rna_tf32(t[x][y + i]);
}

// ---------------- tf32 mma.sync GEMM: C[M,N] = A[M,K] * B[N,K]^T ----------
// CTA tile 256x128x32, 8 warps (4m x 2n), warp tile 64x64, 3-stage cp.async
// pipeline. SMEM row stride 36 floats -> conflict-free fragment loads.
// EPI: 0=none 1=alpha 2=bias+relu 3=bias+res 4=res.
#define BM 256
#define BN 128
#define BK 32
#define SST 36                          // smem row stride (floats)
static constexpr int TILE_A_BYTES = BM * SST * 4;          // 36864
static constexpr int TILE_B_BYTES = BN * SST * 4;          // 18432
static constexpr int STAGE_BYTES  = TILE_A_BYTES + TILE_B_BYTES;  // 55296
static constexpr int NSTAGE       = 3;
static constexpr int SMEM_TOT     = NSTAGE * STAGE_BYTES;  // 165888

template <int EPI, bool RND, bool CSKIP, bool KLIM>
__global__ __launch_bounds__(256)
void mma_gemm(const float* __restrict__ Ag, const float* __restrict__ Bg,
              float* __restrict__ Cg, const float* __restrict__ bias,
              const float* __restrict__ Rg,
              int K, int lda, int ldb, int ldc,
              long long sA, long long sB, long long sC, long long sR,
              float alpha)
{
    const int m0 = blockIdx.y * BM, n0 = blockIdx.x * BN, bz = blockIdx.z;
    if (CSKIP && n0 >= m0 + BM) return;
    Ag += (size_t)bz * sA;
    Bg += (size_t)bz * sB;
    Cg += (size_t)bz * sC;
    if (EPI == 3 || EPI == 4) Rg += (size_t)bz * sR;

    extern __shared__ char smem[];
    const uint32_t sb = smem_u32(smem);
    float* sf = (float*)smem;

    const int tid  = threadIdx.x;
    const int wid  = tid >> 5;
    const int lane = tid & 31;
    const int wm   = (wid >> 1) * 64;    // warp m offset (0,64,128,192)
    const int wn   = (wid & 1) * 64;     // warp n offset (0,64)
    const int lr   = lane >> 2;          // 0..7
    const int lc   = lane & 3;           // 0..3

    int kend = K;
    if (KLIM) { int lim = m0 + BM; kend = lim < K ? lim : K; }
    const int T = kend >> 5;

    float acc[4][8][4];
    #pragma unroll
    for (int mi = 0; mi < 4; mi++)
        #pragma unroll
        for (int ni = 0; ni < 8; ni++)
            #pragma unroll
            for (int q = 0; q < 4; q++) acc[mi][ni][q] = 0.f;

    // A: 256 rows x 8 float4-chunks = 2048 chunks; 8 per thread
    auto cpA = [&](int t, int slot) {
        const float* base = Ag + (size_t)m0 * lda + t * BK;
        const uint32_t db = sb + slot * STAGE_BYTES;
        #pragma unroll
        for (int it = 0; it < 8; it++) {
            const int idx = tid + it * 256;
            const int r = idx >> 3, c4 = idx & 7;
            cpa16(db + (uint32_t)(r * (SST * 4) + c4 * 16),
                  base + (size_t)r * lda + c4 * 4);
        }
    };
    // B: 128 rows x 8 chunks = 1024 chunks; 4 per thread
    auto cpB = [&](int t, int slot) {
        const float* base = Bg + (size_t)n0 * ldb + t * BK;
        const uint32_t db = sb + slot * STAGE_BYTES + TILE_A_BYTES;
        #pragma unroll
        for (int it = 0; it < 4; it++) {
            const int idx = tid + it * 256;
            const int r = idx >> 3, c4 = idx & 7;
            cpa16(db + (uint32_t)(r * (SST * 4) + c4 * 16),
                  base + (size_t)r * ldb + c4 * 4);
        }
    };

    // prologue: stages 0 and 1, separate commit groups
    cpA(0, 0); cpB(0, 0); cp_commit();
    if (T > 1) { cpA(1, 1); cpB(1, 1); cp_commit(); }

    int slot = 0;
    for (int i = 0; i < T; i++) {
        if (i < T - 1) cp_wait1(); else cp_wait0();
        __syncthreads();

        const float* sa  = sf + (size_t)slot * (STAGE_BYTES / 4);
        const float* sbb = sa + (TILE_A_BYTES / 4);

        #pragma unroll
        for (int ks = 0; ks < 4; ks++) {
            const int kb = ks * 8;
            uint32_t af[4][4];
            #pragma unroll
            for (int mi = 0; mi < 4; mi++) {
                const int r = wm + mi * 16 + lr;
                af[mi][0] = __float_as_uint(sa[(r    ) * SST + kb + lc    ]);
                af[mi][1] = __float_as_uint(sa[(r + 8) * SST + kb + lc    ]);
                af[mi][2] = __float_as_uint(sa[(r    ) * SST + kb + lc + 4]);
                af[mi][3] = __float_as_uint(sa[(r + 8) * SST + kb + lc + 4]);
            }
            uint32_t bf[8][2];
            #pragma unroll
            for (int ni = 0; ni < 8; ni++) {
                const int n = wn + ni * 8 + lr;
                bf[ni][0] = __float_as_uint(sbb[n * SST + kb + lc    ]);
                bf[ni][1] = __float_as_uint(sbb[n * SST + kb + lc + 4]);
            }
            #pragma unroll
            for (int mi = 0; mi < 4; mi++)
                #pragma unroll
                for (int ni = 0; ni < 8; ni++)
                    mma_tf32_16n8k8(acc[mi][ni][0], acc[mi][ni][1],
                                    acc[mi][ni][2], acc[mi][ni][3],
                                    af[mi][0], af[mi][1], af[mi][2], af[mi][3],
                                    bf[ni][0], bf[ni][1]);
        }

        // prefetch stage i+2 into the slot freed by iteration i-1
        if (i + 2 < T) {
            const int ns = (slot + 2) % NSTAGE;
            cpA(i + 2, ns); cpB(i + 2, ns); cp_commit();
        }
        slot = (slot + 1) % NSTAGE;
    }

    // ---- epilogue: d0,d1 -> (row, col..col+1); d2,d3 -> (row+8, ...) ----
    #pragma unroll
    for (int mi = 0; mi < 4; mi++) {
        const int r0 = m0 + wm + mi * 16 + lr;
        #pragma unroll
        for (int ni = 0; ni < 8; ni++) {
            const int col = n0 + wn + ni * 8 + 2 * lc;
            #pragma unroll
            for (int h = 0; h < 2; h++) {
                const int r = r0 + h * 8;
                float vx = acc[mi][ni][2 * h + 0];
                float vy = acc[mi][ni][2 * h + 1];
                const size_t off = (size_t)r * ldc + col;
                if (EPI == 1) {
                    vx *= alpha; vy *= alpha;
                } else if (EPI == 2) {
                    vx = fmaxf(vx + __ldg(bias + col + 0), 0.f);
                    vy = fmaxf(vy + __ldg(bias + col + 1), 0.f);
                } else if (EPI == 3) {
                    float2 rr = *(const float2*)(Rg + off);
                    vx += __ldg(bias + col + 0) + rr.x;
                    vy += __ldg(bias + col + 1) + rr.y;
                } else if (EPI == 4) {
                    float2 rr = *(const float2*)(Rg + off);
                    vx += rr.x; vy += rr.y;
                }
                if (RND) { vx = rna_tf32(vx); vy = rna_tf32(vy); }
                float2 o2; o2.x = vx; o2.y = vy;
                *(float2*)(Cg + off) = o2;
            }
        }
    }
}

// ---------------- launcher ------------------------------------------------
extern "C" void kernel_launch(void* const* d_in, const int* in_sizes, int n_in,
                              void* d_out, int out_size)
{
    (void)in_sizes; (void)n_in; (void)out_size;
    const float* x      = (const float*)d_in[0];
    const float* Qw     = (const float*)d_in[1];
    const float* Kw     = (const float*)d_in[2];
    const float* Vw     = (const float*)d_in[3];
    const float* w1     = (const float*)d_in[4];
    const float* b1     = (const float*)d_in[5];
    const float* w2     = (const float*)d_in[6];
    const float* b2     = (const float*)d_in[7];
    const float* gamma1 = (const float*)d_in[8];
    const float* beta1  = (const float*)d_in[9];
    const float* gamma2 = (const float*)d_in[10];
    const float* beta2  = (const float*)d_in[11];
    float* out = (float*)d_out;

    float *pln1, *pQ, *pK, *pVt, *pS, *px1, *pln2, *pH;
    float *pQwt, *pKwt, *pVwt, *pw1t, *pw2t;
    cudaGetSymbolAddress((void**)&pln1, g_ln1);
    cudaGetSymbolAddress((void**)&pQ,   g_Q);
    cudaGetSymbolAddress((void**)&pK,   g_K);
    cudaGetSymbolAddress((void**)&pVt,  g_Vt);
    cudaGetSymbolAddress((void**)&pS,   g_S);
    cudaGetSymbolAddress((void**)&px1,  g_x1);
    cudaGetSymbolAddress((void**)&pln2, g_ln2);
    cudaGetSymbolAddress((void**)&pH,   g_H);
    cudaGetSymbolAddress((void**)&pQwt, g_Qwt);
    cudaGetSymbolAddress((void**)&pKwt, g_Kwt);
    cudaGetSymbolAddress((void**)&pVwt, g_Vwt);
    cudaGetSymbolAddress((void**)&pw1t, g_w1t);
    cudaGetSymbolAddress((void**)&pw2t, g_w2t);

    cudaFuncSetAttribute(mma_gemm<0, true,  false, false>,
        cudaFuncAttributeMaxDynamicSharedMemorySize, SMEM_TOT);
    cudaFuncSetAttribute(mma_gemm<1, false, true,  false>,
        cudaFuncAttributeMaxDynamicSharedMemorySize, SMEM_TOT);
    cudaFuncSetAttribute(mma_gemm<4, false, false, true>,
        cudaFuncAttributeMaxDynamicSharedMemorySize, SMEM_TOT);
    cudaFuncSetAttribute(mma_gemm<2, true,  false, false>,
        cudaFuncAttributeMaxDynamicSharedMemorySize, SMEM_TOT);
    cudaFuncSetAttribute(mma_gemm<3, false, false, false>,
        cudaFuncAttributeMaxDynamicSharedMemorySize, SMEM_TOT);

    const int MR = BB * SS;                 // 8192
    const long long SD  = (long long)SS * DD;
    const long long SSq = (long long)SS * SS;
    const long long DS  = (long long)DD * SS;
    dim3 tb(32, 8);

    // 0) weight transposes (K-major B operands), rounded to tf32
    transpose_kernel<<<dim3(DD / 32, DD / 32), tb>>>(Qw, pQwt, DD, DD);
    transpose_kernel<<<dim3(DD / 32, DD / 32), tb>>>(Kw, pKwt, DD, DD);
    transpose_kernel<<<dim3(DD / 32, DD / 32), tb>>>(Vw, pVwt, DD, DD);
    transpose_kernel<<<dim3(FF / 32, DD / 32), tb>>>(w1, pw1t, DD, FF);
    transpose_kernel<<<dim3(DD / 32, FF / 32), tb>>>(w2, pw2t, FF, DD);

    // 1) LN1
    layernorm_kernel<<<MR, 256>>>(x, gamma1, beta1, pln1);

    // 2) Q = ln1 @ Qw ; K = ln1 @ Kw   (M=8192, N=1024, K=1024)
    dim3 gq(DD / BN, MR / BM, 1);
    mma_gemm<0, true, false, false><<<gq, 256, SMEM_TOT>>>(
        pln1, pQwt, pQ, nullptr, nullptr, DD, DD, DD, DD, 0, 0, 0, 0, 1.f);
    mma_gemm<0, true, false, false><<<gq, 256, SMEM_TOT>>>(
        pln1, pKwt, pK, nullptr, nullptr, DD, DD, DD, DD, 0, 0, 0, 0, 1.f);

    // 3) Vt[b,d,s] = sum_k Vwt[d,k] * ln1[b,s,k]   (M=1024, N=2048 per batch)
    dim3 gv(SS / BN, DD / BM, BB);
    mma_gemm<0, true, false, false><<<gv, 256, SMEM_TOT>>>(
        pVwt, pln1, pVt, nullptr, nullptr, DD, DD, DD, SS, 0, SD, DS, 0, 1.f);

    // 4) scores = Q @ K^T / 32, causal tiles only  (M=N=2048, K=1024)
    dim3 gs(SS / BN, SS / BM, BB);
    mma_gemm<1, false, true, false><<<gs, 256, SMEM_TOT>>>(
        pQ, pK, pS, nullptr, nullptr, DD, DD, DD, SS, SD, SD, SSq, 0, 0.03125f);

    // 5) causal softmax (rounded, zero-padded to 256 boundary)
    softmax_kernel<<<MR, 256>>>(pS);

    // 6) x1 = P @ V + x    (M=2048, N=1024, K<=row band, per batch)
    dim3 gp(DD / BN, SS / BM, BB);
    mma_gemm<4, false, false, true><<<gp, 256, SMEM_TOT>>>(
        pS, pVt, px1, nullptr, x, SS, SS, SS, DD, SSq, DS, SD, SD, 1.f);

    // 7) LN2
    layernorm_kernel<<<MR, 256>>>(px1, gamma2, beta2, pln2);

    // 8) H = relu(ln2 @ w1 + b1)   (M=8192, N=4096, K=1024)
    dim3 g1(FF / BN, MR / BM, 1);
    mma_gemm<2, true, false, false><<<g1, 256, SMEM_TOT>>>(
        pln2, pw1t, pH, b1, nullptr, DD, DD, DD, FF, 0, 0, 0, 0, 1.f);

    // 9) out = H @ w2 + b2 + x1    (M=8192, N=1024, K=4096)
    dim3 g2(DD / BN, MR / BM, 1);
    mma_gemm<3, false, false, false><<<g2, 256, SMEM_TOT>>>(
        pH, pw2t, out, b2, px1, FF, FF, FF, DD, 0, 0, 0, 0, 1.f);
}